// round 14
// baseline (speedup 1.0000x reference)
#include <cuda_runtime.h>

#define BB 2
#define SS 512
#define DD 256
#define BS (BB*SS)
#define NT 16            // 512/32 j-tiles per dim
#define NP 136           // NT*(NT+1)/2 triangular tile pairs

// Scratch (allocation-free rule: __device__ globals).
__device__ float g_WT[DD*DD];     // W transposed: [k][e] = W[e][k]
__device__ float g_ET[BB*DD*SS];  // E transposed: [b][e][j] = exp(2*P[b][j][e])
__device__ float g_R [BS*DD];     // R row-major:  [r][e]    = exp(-2*P[r][e])
__device__ float g_S [BS*SS];     // EXP scores   [r][j] = exp(sjt[r][j])
__device__ float g_sum[BS];       // softmax denominators per row

__device__ __forceinline__ float frcp_approx(float x){
    float r; asm("rcp.approx.f32 %0, %1;" : "=f"(r) : "f"(x)); return r;
}

// K0: WT[k][e] = W[e][k]; block 0 also zeroes g_sum (for graph replays).
__global__ void __launch_bounds__(256) k0_wt(const float* __restrict__ W){
    __shared__ float t[32][33];
    const int bx = blockIdx.x & 7, by = blockIdx.x >> 3;
    const int lx = threadIdx.x & 31, ly = threadIdx.x >> 5;  // ly 0..7
    if (blockIdx.x == 0) {
        #pragma unroll
        for (int r = threadIdx.x; r < BS; r += 256) g_sum[r] = 0.f;
    }
    #pragma unroll
    for (int r = 0; r < 4; r++)
        t[ly + 8*r][lx] = W[(by*32 + ly + 8*r) * DD + bx*32 + lx];
    __syncthreads();
    #pragma unroll
    for (int r = 0; r < 4; r++)
        g_WT[(bx*32 + ly + 8*r) * DD + by*32 + lx] = t[lx][ly + 8*r];
}

// K1: P = Q @ Wm^T via WT (coalesced L2 reads). i-tile 4, grid 256.
__global__ void __launch_bounds__(256) k1_proj(const float* __restrict__ Q){
    __shared__ __align__(16) float sQT[DD][4];
    const int tid = threadIdx.x;
    const int r0  = blockIdx.x * 4;

    #pragma unroll
    for (int m = 0; m < 4; m++) sQT[tid][m] = Q[(r0 + m) * DD + tid];
    __syncthreads();

    float acc[4] = {0,0,0,0};
    const float* wt = g_WT + tid;
    #pragma unroll 8
    for (int k = 0; k < DD; k++) {
        float wv = __ldg(wt + k * DD);
        float4 q0 = *(const float4*)&sQT[k][0];
        acc[0] = fmaf(wv, q0.x, acc[0]); acc[1] = fmaf(wv, q0.y, acc[1]);
        acc[2] = fmaf(wv, q0.z, acc[2]); acc[3] = fmaf(wv, q0.w, acc[3]);
    }

    const float C2 = 2.885390081777927f; // 2*log2(e)
    const int b  = r0 / SS;
    const int jr = r0 % SS;
    #pragma unroll
    for (int m = 0; m < 4; m++) {
        float p = acc[m];
        g_ET[(size_t)b * DD * SS + (size_t)tid * SS + (jr + m)] = exp2f( C2 * p);
        g_R [(size_t)(r0 + m) * DD + tid]                       = exp2f(-C2 * p);
    }
}

// K2s: EXP-scores for one 32x32 tile pair (ti<=tj) via antisymmetry.
// Direct tile: exp(s). Transposed tile: rcp(exp(s)) = exp(-s).
// Also accumulates softmax row sums into g_sum via atomics.
__global__ void __launch_bounds__(256) k2_scores(const float* __restrict__ vm){
    __shared__ __align__(16) float sR[32][260];   // R tile; reused after e-loop
    __shared__ float sm2[256];
    __shared__ float s_red[8];

    const int tid  = threadIdx.x;
    const int lane = tid & 31;
    const int w    = tid >> 5;
    const int b    = blockIdx.x / NP;
    int p = blockIdx.x - b * NP;
    int ti = 0;
    while (p >= NT - ti) { p -= NT - ti; ti++; }
    const int tj = ti + p;
    const int I = ti * 32, J = tj * 32;

    {
        float vme = vm[tid];
        sm2[tid] = -2.f * vme;
        float svp = vme;
        #pragma unroll
        for (int off = 16; off; off >>= 1) svp += __shfl_xor_sync(0xffffffffu, svp, off);
        if (lane == 0) s_red[w] = svp;
    }
    {
        const float4* R4 = (const float4*)(g_R + (size_t)(b * SS + I) * DD);
        #pragma unroll
        for (int k = 0; k < 8; k++) {
            int lin = k * 256 + tid;
            int row = lin >> 6;
            int c4  = lin & 63;
            float4 v = R4[row * 64 + c4];
            *(float4*)&sR[row][c4 * 4] = v;
        }
    }
    __syncthreads();
    const float sv = s_red[0] + s_red[1] + s_red[2] + s_red[3] +
                     s_red[4] + s_red[5] + s_red[6] + s_red[7];

    const int grp  = tid >> 7;
    const int t    = tid & 127;
    const int i    = t >> 2;
    const int col0 = tj * 8 + (t & 3) * 2;

    float4 acc0 = {0,0,0,0}, acc1 = {0,0,0,0};
    {
        const float4* EB = (const float4*)(g_ET + (size_t)b * DD * SS);
        const int e0 = grp * 128;
        const float4* pe = EB + (size_t)e0 * (SS/4) + col0;
        float4 n0 = pe[0],   n1 = pe[1];
        float4 n2 = pe[128], n3 = pe[129];
        float4 n4 = pe[256], n5 = pe[257];
        float4 n6 = pe[384], n7 = pe[385];
        pe += 512;

        for (int chunk = 0; chunk < 32; chunk++) {
            float4 c0=n0,c1=n1,c2=n2,c3=n3,c4=n4,c5=n5,c6=n6,c7=n7;
            if (chunk < 31) {
                n0=pe[0];   n1=pe[1];
                n2=pe[128]; n3=pe[129];
                n4=pe[256]; n5=pe[257];
                n6=pe[384]; n7=pe[385];
                pe += 512;
            }
            const int e = e0 + chunk * 4;
            float4 r4 = *(const float4*)&sR[i][e];
            float4 m4 = *(const float4*)&sm2[e];

            acc0.x = fmaf(m4.x, frcp_approx(fmaf(c0.x, r4.x, 1.f)), acc0.x);
            acc0.y = fmaf(m4.x, frcp_approx(fmaf(c0.y, r4.x, 1.f)), acc0.y);
            acc0.z = fmaf(m4.x, frcp_approx(fmaf(c0.z, r4.x, 1.f)), acc0.z);
            acc0.w = fmaf(m4.x, frcp_approx(fmaf(c0.w, r4.x, 1.f)), acc0.w);
            acc1.x = fmaf(m4.x, frcp_approx(fmaf(c1.x, r4.x, 1.f)), acc1.x);
            acc1.y = fmaf(m4.x, frcp_approx(fmaf(c1.y, r4.x, 1.f)), acc1.y);
            acc1.z = fmaf(m4.x, frcp_approx(fmaf(c1.z, r4.x, 1.f)), acc1.z);
            acc1.w = fmaf(m4.x, frcp_approx(fmaf(c1.w, r4.x, 1.f)), acc1.w);

            acc0.x = fmaf(m4.y, frcp_approx(fmaf(c2.x, r4.y, 1.f)), acc0.x);
            acc0.y = fmaf(m4.y, frcp_approx(fmaf(c2.y, r4.y, 1.f)), acc0.y);
            acc0.z = fmaf(m4.y, frcp_approx(fmaf(c2.z, r4.y, 1.f)), acc0.z);
            acc0.w = fmaf(m4.y, frcp_approx(fmaf(c2.w, r4.y, 1.f)), acc0.w);
            acc1.x = fmaf(m4.y, frcp_approx(fmaf(c3.x, r4.y, 1.f)), acc1.x);
            acc1.y = fmaf(m4.y, frcp_approx(fmaf(c3.y, r4.y, 1.f)), acc1.y);
            acc1.z = fmaf(m4.y, frcp_approx(fmaf(c3.z, r4.y, 1.f)), acc1.z);
            acc1.w = fmaf(m4.y, frcp_approx(fmaf(c3.w, r4.y, 1.f)), acc1.w);

            acc0.x = fmaf(m4.z, frcp_approx(fmaf(c4.x, r4.z, 1.f)), acc0.x);
            acc0.y = fmaf(m4.z, frcp_approx(fmaf(c4.y, r4.z, 1.f)), acc0.y);
            acc0.z = fmaf(m4.z, frcp_approx(fmaf(c4.z, r4.z, 1.f)), acc0.z);
            acc0.w = fmaf(m4.z, frcp_approx(fmaf(c4.w, r4.z, 1.f)), acc0.w);
            acc1.x = fmaf(m4.z, frcp_approx(fmaf(c5.x, r4.z, 1.f)), acc1.x);
            acc1.y = fmaf(m4.z, frcp_approx(fmaf(c5.y, r4.z, 1.f)), acc1.y);
            acc1.z = fmaf(m4.z, frcp_approx(fmaf(c5.z, r4.z, 1.f)), acc1.z);
            acc1.w = fmaf(m4.z, frcp_approx(fmaf(c5.w, r4.z, 1.f)), acc1.w);

            acc0.x = fmaf(m4.w, frcp_approx(fmaf(c6.x, r4.w, 1.f)), acc0.x);
            acc0.y = fmaf(m4.w, frcp_approx(fmaf(c6.y, r4.w, 1.f)), acc0.y);
            acc0.z = fmaf(m4.w, frcp_approx(fmaf(c6.z, r4.w, 1.f)), acc0.z);
            acc0.w = fmaf(m4.w, frcp_approx(fmaf(c6.w, r4.w, 1.f)), acc0.w);
            acc1.x = fmaf(m4.w, frcp_approx(fmaf(c7.x, r4.w, 1.f)), acc1.x);
            acc1.y = fmaf(m4.w, frcp_approx(fmaf(c7.y, r4.w, 1.f)), acc1.y);
            acc1.z = fmaf(m4.w, frcp_approx(fmaf(c7.z, r4.w, 1.f)), acc1.z);
            acc1.w = fmaf(m4.w, frcp_approx(fmaf(c7.w, r4.w, 1.f)), acc1.w);
        }
    }

    // Reuse sR storage: sp0[1024] | sp1[1024] | st[32][36]
    float* sp0 = &sR[0][0];
    float* sp1 = sp0 + 1024;
    float (*st)[36] = (float(*)[36])(sp1 + 1024);
    __syncthreads();                       // done reading sR
    {
        float* sp = grp ? sp1 : sp0;
        *(float4*)&sp[i * 32 + (t & 3) * 8]     = acc0;
        *(float4*)&sp[i * 32 + (t & 3) * 8 + 4] = acc1;
    }
    __syncthreads();
    {
        const int ii = tid >> 3, j0 = (tid & 7) * 4;
        float4 a  = *(const float4*)&sp0[ii * 32 + j0];
        float4 bb = *(const float4*)&sp1[ii * 32 + j0];
        float4 es;
        es.x = __expf(a.x + bb.x + sv);
        es.y = __expf(a.y + bb.y + sv);
        es.z = __expf(a.z + bb.z + sv);
        es.w = __expf(a.w + bb.w + sv);
        *(float4*)&st[ii][j0] = es;
        *(float4*)&g_S[(size_t)(b * SS + I + ii) * SS + J + j0] = es;
        float rs = es.x + es.y + es.z + es.w;
        rs += __shfl_xor_sync(0xffffffffu, rs, 4);
        rs += __shfl_xor_sync(0xffffffffu, rs, 2);
        rs += __shfl_xor_sync(0xffffffffu, rs, 1);
        if ((tid & 7) == 0) atomicAdd(&g_sum[b * SS + I + ii], rs);
    }
    if (ti != tj) {
        __syncthreads();
        const int j = tid >> 3, i0 = (tid & 7) * 4;
        float4 mv = make_float4(frcp_approx(st[i0 + 0][j]), frcp_approx(st[i0 + 1][j]),
                                frcp_approx(st[i0 + 2][j]), frcp_approx(st[i0 + 3][j]));
        *(float4*)&g_S[(size_t)(b * SS + J + j) * SS + I + i0] = mv;
        float rs = mv.x + mv.y + mv.z + mv.w;
        rs += __shfl_xor_sync(0xffffffffu, rs, 4);
        rs += __shfl_xor_sync(0xffffffffu, rs, 2);
        rs += __shfl_xor_sync(0xffffffffu, rs, 1);
        if ((tid & 7) == 0) atomicAdd(&g_sum[b * SS + J + j], rs);
    }
}

// K3: normalize + AV, 16-row tiles, software-pipelined (double-buffered sA/sV,
// register prefetch 2 chunks ahead, ONE sync per chunk).
// grid = 64 row-tiles x 8 d-tiles = 512 blocks (3.5 blocks/SM).
// Warp-pair group jg owns 16 j per 64-chunk; lane = (ig 0..7, d4 0..7);
// 2x register i-tiling: rows {ig, ig+8}. dt==0 writes atten at store time.
__global__ void __launch_bounds__(256) k3_av(const float* __restrict__ V,
                                             float* __restrict__ out_ctx,
                                             float* __restrict__ out_att){
    __shared__ __align__(16) float sA[2][16][68];
    __shared__ __align__(16) float sV[2][64][36];
    __shared__ float sInv[16];
    __shared__ __align__(16) float sP[4][64][4];   // jg-partial combine

    const int tid = threadIdx.x;
    const int rt  = blockIdx.x >> 3;
    const int dt  = blockIdx.x & 7;
    const int r0  = rt * 16;
    const int b   = r0 >> 9;
    const int jb  = b << 9;
    const int d0  = dt * 32;
    const int si  = tid >> 4;        // staging row (0..15)
    const int js  = tid & 15;        // float4 index within 64-j chunk
    const int jv  = tid >> 2;        // V staging row
    const int c8  = (tid & 3) * 8;

    if (tid < 16) sInv[tid] = 1.f / g_sum[r0 + tid];
    __syncthreads();
    const float invs = sInv[si];

    const float* Srow  = g_S + (size_t)(r0 + si) * SS + js * 4;
    const float* Vbase = V + (size_t)(jb + jv) * DD + d0 + c8;

    float4 pa, pv0, pv1;

    // ---- prologue: load chunk 0, store to buf 0, load chunk 1 ----
    pa  = *(const float4*)(Srow);
    pv0 = *(const float4*)Vbase; pv1 = *(const float4*)(Vbase + 4);
    {
        float4 v0 = pa;
        v0.x *= invs; v0.y *= invs; v0.z *= invs; v0.w *= invs;
        *(float4*)&sA[0][si][js * 4] = v0;
        if (dt == 0)
            *(float4*)&out_att[(size_t)(r0 + si) * SS + js * 4] = v0;
        *(float4*)&sV[0][jv][c8]     = pv0;
        *(float4*)&sV[0][jv][c8 + 4] = pv1;
    }
    pa  = *(const float4*)(Srow + 64);
    pv0 = *(const float4*)(Vbase + (size_t)64 * DD);
    pv1 = *(const float4*)(Vbase + (size_t)64 * DD + 4);
    __syncthreads();

    // AV mapping
    const int jg = tid >> 6;         // 0..3
    const int s  = tid & 63;
    const int ig = s >> 3;           // 0..7
    const int d4 = s & 7;
    float4 acc[2];
    acc[0] = make_float4(0,0,0,0);
    acc[1] = make_float4(0,0,0,0);

    for (int jc = 0; jc < 8; jc++) {
        const int bf = jc & 1;
        if (jc < 7) {
            float4 v0 = pa;
            v0.x *= invs; v0.y *= invs; v0.z *= invs; v0.w *= invs;
            *(float4*)&sA[1 - bf][si][js * 4] = v0;
            if (dt == 0)
                *(float4*)&out_att[(size_t)(r0 + si) * SS + (jc + 1) * 64 + js * 4] = v0;
            *(float4*)&sV[1 - bf][jv][c8]     = pv0;
            *(float4*)&sV[1 - bf][jv][c8 + 4] = pv1;
        }
        if (jc < 6) {
            pa  = *(const float4*)(Srow + (jc + 2) * 64);
            const float* Vp = Vbase + (size_t)((jc + 2) * 64) * DD;
            pv0 = *(const float4*)Vp; pv1 = *(const float4*)(Vp + 4);
        }
        #pragma unroll 4
        for (int jj = 0; jj < 16; jj++) {
            const int j = jg * 16 + jj;
            float4 v4 = *(const float4*)&sV[bf][j][d4 * 4];
            float a0 = sA[bf][ig    ][j];
            float a1 = sA[bf][ig + 8][j];
            acc[0].x = fmaf(a0, v4.x, acc[0].x); acc[0].y = fmaf(a0, v4.y, acc[0].y);
            acc[0].z = fmaf(a0, v4.z, acc[0].z); acc[0].w = fmaf(a0, v4.w, acc[0].w);
            acc[1].x = fmaf(a1, v4.x, acc[1].x); acc[1].y = fmaf(a1, v4.y, acc[1].y);
            acc[1].z = fmaf(a1, v4.z, acc[1].z); acc[1].w = fmaf(a1, v4.w, acc[1].w);
        }
        __syncthreads();
    }

    // combine jg partials, one i-row-group at a time
    #pragma unroll
    for (int r = 0; r < 2; r++) {
        *(float4*)sP[jg][s] = acc[r];
        __syncthreads();
        if (jg == 0) {
            float4 t0 = *(const float4*)sP[0][s];
            float4 t1 = *(const float4*)sP[1][s];
            float4 t2 = *(const float4*)sP[2][s];
            float4 t3 = *(const float4*)sP[3][s];
            float4 o = make_float4(t0.x + t1.x + t2.x + t3.x,
                                   t0.y + t1.y + t2.y + t3.y,
                                   t0.z + t1.z + t2.z + t3.z,
                                   t0.w + t1.w + t2.w + t3.w);
            *(float4*)&out_ctx[(size_t)(r0 + ig + 8 * r) * DD + d0 + d4 * 4] = o;
        }
        __syncthreads();
    }
}

extern "C" void kernel_launch(void* const* d_in, const int* in_sizes, int n_in,
                              void* d_out, int out_size) {
    (void)in_sizes; (void)n_in; (void)out_size;
    const float* Q  = (const float*)d_in[0];
    const float* V  = (const float*)d_in[2];
    const float* Wm = (const float*)d_in[3];
    const float* vm = (const float*)d_in[4];
    float* out      = (float*)d_out;
    float* out_ctx  = out;              // context [B,S,D]
    float* out_att  = out + BS * DD;    // atten   [B,S,S]

    k0_wt    <<<64, 256>>>(Wm);
    k1_proj  <<<BS / 4, 256>>>(Q);
    k2_scores<<<BB * NP, 256>>>(vm);
    k3_av    <<<(BS / 16) * 8, 256>>>(V, out_ctx, out_att);
}

// round 15
// speedup vs baseline: 1.0607x; 1.0607x over previous
#include <cuda_runtime.h>

#define BB 2
#define SS 512
#define DD 256
#define BS (BB*SS)
#define NT 16            // 512/32 j-tiles per dim
#define NP 136           // NT*(NT+1)/2 triangular tile pairs

// Scratch (allocation-free rule: __device__ globals).
__device__ float g_WT[DD*DD];     // W transposed: [k][e] = W[e][k]
__device__ float g_ET[BB*DD*SS];  // E transposed: [b][e][j] = exp(2*P[b][j][e])
__device__ float g_R [BS*DD];     // R row-major:  [r][e]    = exp(-2*P[r][e])
__device__ float g_S [BS*SS];     // EXP scores   [r][j] = exp(sjt[r][j])
__device__ float g_sum[BS];       // softmax denominators per row

__device__ __forceinline__ float frcp_approx(float x){
    float r; asm("rcp.approx.f32 %0, %1;" : "=f"(r) : "f"(x)); return r;
}

// K0: WT[k][e] = W[e][k]; block 0 also zeroes g_sum (for graph replays).
__global__ void __launch_bounds__(256) k0_wt(const float* __restrict__ W){
    __shared__ float t[32][33];
    const int bx = blockIdx.x & 7, by = blockIdx.x >> 3;
    const int lx = threadIdx.x & 31, ly = threadIdx.x >> 5;  // ly 0..7
    if (blockIdx.x == 0) {
        #pragma unroll
        for (int r = threadIdx.x; r < BS; r += 256) g_sum[r] = 0.f;
    }
    #pragma unroll
    for (int r = 0; r < 4; r++)
        t[ly + 8*r][lx] = W[(by*32 + ly + 8*r) * DD + bx*32 + lx];
    __syncthreads();
    #pragma unroll
    for (int r = 0; r < 4; r++)
        g_WT[(bx*32 + ly + 8*r) * DD + by*32 + lx] = t[lx][ly + 8*r];
}

// K1: P = Q @ Wm^T via WT (coalesced L2 reads). i-tile 4, grid 256.
__global__ void __launch_bounds__(256) k1_proj(const float* __restrict__ Q){
    __shared__ __align__(16) float sQT[DD][4];
    const int tid = threadIdx.x;
    const int r0  = blockIdx.x * 4;

    #pragma unroll
    for (int m = 0; m < 4; m++) sQT[tid][m] = Q[(r0 + m) * DD + tid];
    __syncthreads();

    float acc[4] = {0,0,0,0};
    const float* wt = g_WT + tid;
    #pragma unroll 8
    for (int k = 0; k < DD; k++) {
        float wv = __ldg(wt + k * DD);
        float4 q0 = *(const float4*)&sQT[k][0];
        acc[0] = fmaf(wv, q0.x, acc[0]); acc[1] = fmaf(wv, q0.y, acc[1]);
        acc[2] = fmaf(wv, q0.z, acc[2]); acc[3] = fmaf(wv, q0.w, acc[3]);
    }

    const float C2 = 2.885390081777927f; // 2*log2(e)
    const int b  = r0 / SS;
    const int jr = r0 % SS;
    #pragma unroll
    for (int m = 0; m < 4; m++) {
        float p = acc[m];
        g_ET[(size_t)b * DD * SS + (size_t)tid * SS + (jr + m)] = exp2f( C2 * p);
        g_R [(size_t)(r0 + m) * DD + tid]                       = exp2f(-C2 * p);
    }
}

// K2s: EXP-scores for one 32x32 tile pair (ti<=tj) via antisymmetry.
// Direct tile: exp(s). Transposed tile: rcp(exp(s)) = exp(-s).
// Also accumulates softmax row sums into g_sum via atomics.
__global__ void __launch_bounds__(256) k2_scores(const float* __restrict__ vm){
    __shared__ __align__(16) float sR[32][260];   // R tile; reused after e-loop
    __shared__ float sm2[256];
    __shared__ float s_red[8];

    const int tid  = threadIdx.x;
    const int lane = tid & 31;
    const int w    = tid >> 5;
    const int b    = blockIdx.x / NP;
    int p = blockIdx.x - b * NP;
    int ti = 0;
    while (p >= NT - ti) { p -= NT - ti; ti++; }
    const int tj = ti + p;
    const int I = ti * 32, J = tj * 32;

    {
        float vme = vm[tid];
        sm2[tid] = -2.f * vme;
        float svp = vme;
        #pragma unroll
        for (int off = 16; off; off >>= 1) svp += __shfl_xor_sync(0xffffffffu, svp, off);
        if (lane == 0) s_red[w] = svp;
    }
    {
        const float4* R4 = (const float4*)(g_R + (size_t)(b * SS + I) * DD);
        #pragma unroll
        for (int k = 0; k < 8; k++) {
            int lin = k * 256 + tid;
            int row = lin >> 6;
            int c4  = lin & 63;
            float4 v = R4[row * 64 + c4];
            *(float4*)&sR[row][c4 * 4] = v;
        }
    }
    __syncthreads();
    const float sv = s_red[0] + s_red[1] + s_red[2] + s_red[3] +
                     s_red[4] + s_red[5] + s_red[6] + s_red[7];

    const int grp  = tid >> 7;
    const int t    = tid & 127;
    const int i    = t >> 2;
    const int col0 = tj * 8 + (t & 3) * 2;

    float4 acc0 = {0,0,0,0}, acc1 = {0,0,0,0};
    {
        const float4* EB = (const float4*)(g_ET + (size_t)b * DD * SS);
        const int e0 = grp * 128;
        const float4* pe = EB + (size_t)e0 * (SS/4) + col0;
        float4 n0 = pe[0],   n1 = pe[1];
        float4 n2 = pe[128], n3 = pe[129];
        float4 n4 = pe[256], n5 = pe[257];
        float4 n6 = pe[384], n7 = pe[385];
        pe += 512;

        for (int chunk = 0; chunk < 32; chunk++) {
            float4 c0=n0,c1=n1,c2=n2,c3=n3,c4=n4,c5=n5,c6=n6,c7=n7;
            if (chunk < 31) {
                n0=pe[0];   n1=pe[1];
                n2=pe[128]; n3=pe[129];
                n4=pe[256]; n5=pe[257];
                n6=pe[384]; n7=pe[385];
                pe += 512;
            }
            const int e = e0 + chunk * 4;
            float4 r4 = *(const float4*)&sR[i][e];
            float4 m4 = *(const float4*)&sm2[e];

            acc0.x = fmaf(m4.x, frcp_approx(fmaf(c0.x, r4.x, 1.f)), acc0.x);
            acc0.y = fmaf(m4.x, frcp_approx(fmaf(c0.y, r4.x, 1.f)), acc0.y);
            acc0.z = fmaf(m4.x, frcp_approx(fmaf(c0.z, r4.x, 1.f)), acc0.z);
            acc0.w = fmaf(m4.x, frcp_approx(fmaf(c0.w, r4.x, 1.f)), acc0.w);
            acc1.x = fmaf(m4.x, frcp_approx(fmaf(c1.x, r4.x, 1.f)), acc1.x);
            acc1.y = fmaf(m4.x, frcp_approx(fmaf(c1.y, r4.x, 1.f)), acc1.y);
            acc1.z = fmaf(m4.x, frcp_approx(fmaf(c1.z, r4.x, 1.f)), acc1.z);
            acc1.w = fmaf(m4.x, frcp_approx(fmaf(c1.w, r4.x, 1.f)), acc1.w);

            acc0.x = fmaf(m4.y, frcp_approx(fmaf(c2.x, r4.y, 1.f)), acc0.x);
            acc0.y = fmaf(m4.y, frcp_approx(fmaf(c2.y, r4.y, 1.f)), acc0.y);
            acc0.z = fmaf(m4.y, frcp_approx(fmaf(c2.z, r4.y, 1.f)), acc0.z);
            acc0.w = fmaf(m4.y, frcp_approx(fmaf(c2.w, r4.y, 1.f)), acc0.w);
            acc1.x = fmaf(m4.y, frcp_approx(fmaf(c3.x, r4.y, 1.f)), acc1.x);
            acc1.y = fmaf(m4.y, frcp_approx(fmaf(c3.y, r4.y, 1.f)), acc1.y);
            acc1.z = fmaf(m4.y, frcp_approx(fmaf(c3.z, r4.y, 1.f)), acc1.z);
            acc1.w = fmaf(m4.y, frcp_approx(fmaf(c3.w, r4.y, 1.f)), acc1.w);

            acc0.x = fmaf(m4.z, frcp_approx(fmaf(c4.x, r4.z, 1.f)), acc0.x);
            acc0.y = fmaf(m4.z, frcp_approx(fmaf(c4.y, r4.z, 1.f)), acc0.y);
            acc0.z = fmaf(m4.z, frcp_approx(fmaf(c4.z, r4.z, 1.f)), acc0.z);
            acc0.w = fmaf(m4.z, frcp_approx(fmaf(c4.w, r4.z, 1.f)), acc0.w);
            acc1.x = fmaf(m4.z, frcp_approx(fmaf(c5.x, r4.z, 1.f)), acc1.x);
            acc1.y = fmaf(m4.z, frcp_approx(fmaf(c5.y, r4.z, 1.f)), acc1.y);
            acc1.z = fmaf(m4.z, frcp_approx(fmaf(c5.z, r4.z, 1.f)), acc1.z);
            acc1.w = fmaf(m4.z, frcp_approx(fmaf(c5.w, r4.z, 1.f)), acc1.w);

            acc0.x = fmaf(m4.w, frcp_approx(fmaf(c6.x, r4.w, 1.f)), acc0.x);
            acc0.y = fmaf(m4.w, frcp_approx(fmaf(c6.y, r4.w, 1.f)), acc0.y);
            acc0.z = fmaf(m4.w, frcp_approx(fmaf(c6.z, r4.w, 1.f)), acc0.z);
            acc0.w = fmaf(m4.w, frcp_approx(fmaf(c6.w, r4.w, 1.f)), acc0.w);
            acc1.x = fmaf(m4.w, frcp_approx(fmaf(c7.x, r4.w, 1.f)), acc1.x);
            acc1.y = fmaf(m4.w, frcp_approx(fmaf(c7.y, r4.w, 1.f)), acc1.y);
            acc1.z = fmaf(m4.w, frcp_approx(fmaf(c7.z, r4.w, 1.f)), acc1.z);
            acc1.w = fmaf(m4.w, frcp_approx(fmaf(c7.w, r4.w, 1.f)), acc1.w);
        }
    }

    // Reuse sR storage: sp0[1024] | sp1[1024] | st[32][36]
    float* sp0 = &sR[0][0];
    float* sp1 = sp0 + 1024;
    float (*st)[36] = (float(*)[36])(sp1 + 1024);
    __syncthreads();                       // done reading sR
    {
        float* sp = grp ? sp1 : sp0;
        *(float4*)&sp[i * 32 + (t & 3) * 8]     = acc0;
        *(float4*)&sp[i * 32 + (t & 3) * 8 + 4] = acc1;
    }
    __syncthreads();
    {
        const int ii = tid >> 3, j0 = (tid & 7) * 4;
        float4 a  = *(const float4*)&sp0[ii * 32 + j0];
        float4 bb = *(const float4*)&sp1[ii * 32 + j0];
        float4 es;
        es.x = __expf(a.x + bb.x + sv);
        es.y = __expf(a.y + bb.y + sv);
        es.z = __expf(a.z + bb.z + sv);
        es.w = __expf(a.w + bb.w + sv);
        *(float4*)&st[ii][j0] = es;
        *(float4*)&g_S[(size_t)(b * SS + I + ii) * SS + J + j0] = es;
        float rs = es.x + es.y + es.z + es.w;
        rs += __shfl_xor_sync(0xffffffffu, rs, 4);
        rs += __shfl_xor_sync(0xffffffffu, rs, 2);
        rs += __shfl_xor_sync(0xffffffffu, rs, 1);
        if ((tid & 7) == 0) atomicAdd(&g_sum[b * SS + I + ii], rs);
    }
    if (ti != tj) {
        __syncthreads();
        const int j = tid >> 3, i0 = (tid & 7) * 4;
        float4 mv = make_float4(frcp_approx(st[i0 + 0][j]), frcp_approx(st[i0 + 1][j]),
                                frcp_approx(st[i0 + 2][j]), frcp_approx(st[i0 + 3][j]));
        *(float4*)&g_S[(size_t)(b * SS + J + j) * SS + I + i0] = mv;
        float rs = mv.x + mv.y + mv.z + mv.w;
        rs += __shfl_xor_sync(0xffffffffu, rs, 4);
        rs += __shfl_xor_sync(0xffffffffu, rs, 2);
        rs += __shfl_xor_sync(0xffffffffu, rs, 1);
        if ((tid & 7) == 0) atomicAdd(&g_sum[b * SS + J + j], rs);
    }
}

// K3: normalize + AV, software-pipelined, 4x4x4 register tile.
// grid = 32 row-tiles x 8 d-tiles = 256. Block 256 = jg4 x rg8 x d4_8.
// Thread: rows {4rg..4rg+3} x 4 j x d-float4. 8 LDS.128 per 64 FMA.
__global__ void __launch_bounds__(256) k3_av(const float* __restrict__ V,
                                             float* __restrict__ out_ctx,
                                             float* __restrict__ out_att){
    __shared__ __align__(16) float sA[2][32][68];
    __shared__ __align__(16) float sV[2][64][36];
    __shared__ float sInv[32];
    __shared__ __align__(16) float sP[4][64][4];   // jg-partial combine

    const int tid = threadIdx.x;
    const int rt  = blockIdx.x >> 3;
    const int dt  = blockIdx.x & 7;
    const int r0  = rt * 32;
    const int b   = r0 >> 9;
    const int jb  = b << 9;
    const int d0  = dt * 32;
    const int si  = tid >> 3;        // staging row
    const int js  = tid & 7;
    const int jv  = tid >> 2;        // V staging row
    const int c8  = (tid & 3) * 8;

    if (tid < 32) sInv[tid] = 1.f / g_sum[r0 + tid];
    __syncthreads();
    const float invs = sInv[si];

    const float* Srow  = g_S + (size_t)(r0 + si) * SS + js * 8;
    const float* Vbase = V + (size_t)(jb + jv) * DD + d0 + c8;

    float4 pa0, pa1, pv0, pv1;

    // ---- prologue: load chunk 0, store to buf 0, load chunk 1 ----
    {
        const float4* S4 = (const float4*)(Srow);
        pa0 = S4[0]; pa1 = S4[1];
        pv0 = *(const float4*)Vbase; pv1 = *(const float4*)(Vbase + 4);
    }
    {
        float4 v0 = pa0, v1 = pa1;
        v0.x *= invs; v0.y *= invs; v0.z *= invs; v0.w *= invs;
        v1.x *= invs; v1.y *= invs; v1.z *= invs; v1.w *= invs;
        *(float4*)&sA[0][si][js * 8]     = v0;
        *(float4*)&sA[0][si][js * 8 + 4] = v1;
        if (dt == 0) {
            float4* O = (float4*)(out_att + (size_t)(r0 + si) * SS + js * 8);
            O[0] = v0; O[1] = v1;
        }
        *(float4*)&sV[0][jv][c8]     = pv0;
        *(float4*)&sV[0][jv][c8 + 4] = pv1;
    }
    {
        const float4* S4 = (const float4*)(Srow + 64);
        pa0 = S4[0]; pa1 = S4[1];
        const float* Vp = Vbase + (size_t)64 * DD;
        pv0 = *(const float4*)Vp; pv1 = *(const float4*)(Vp + 4);
    }
    __syncthreads();

    // AV mapping: jg = j-group (16 j), rg = row-group (4 rows), d4 = d-float4
    const int jg = tid >> 6;         // 0..3
    const int s  = tid & 63;
    const int rg = s >> 3;           // 0..7 -> rows 4rg..4rg+3
    const int d4 = s & 7;
    float4 acc[4];
    #pragma unroll
    for (int r = 0; r < 4; r++) acc[r] = make_float4(0,0,0,0);

    for (int jc = 0; jc < 8; jc++) {
        const int bf = jc & 1;
        if (jc < 7) {
            float4 v0 = pa0, v1 = pa1;
            v0.x *= invs; v0.y *= invs; v0.z *= invs; v0.w *= invs;
            v1.x *= invs; v1.y *= invs; v1.z *= invs; v1.w *= invs;
            *(float4*)&sA[1 - bf][si][js * 8]     = v0;
            *(float4*)&sA[1 - bf][si][js * 8 + 4] = v1;
            if (dt == 0) {
                float4* O = (float4*)(out_att + (size_t)(r0 + si) * SS + (jc + 1) * 64 + js * 8);
                O[0] = v0; O[1] = v1;
            }
            *(float4*)&sV[1 - bf][jv][c8]     = pv0;
            *(float4*)&sV[1 - bf][jv][c8 + 4] = pv1;
        }
        if (jc < 6) {
            const float4* S4 = (const float4*)(Srow + (jc + 2) * 64);
            pa0 = S4[0]; pa1 = S4[1];
            const float* Vp = Vbase + (size_t)((jc + 2) * 64) * DD;
            pv0 = *(const float4*)Vp; pv1 = *(const float4*)(Vp + 4);
        }
        // 4x4x4 tile: per it, 4 a-float4 (over j) + 4 v-float4 -> 64 FMA
        #pragma unroll
        for (int it = 0; it < 4; it++) {
            const int j = jg * 16 + it * 4;
            float4 vA = *(const float4*)&sV[bf][j + 0][d4 * 4];
            float4 vB = *(const float4*)&sV[bf][j + 1][d4 * 4];
            float4 vC = *(const float4*)&sV[bf][j + 2][d4 * 4];
            float4 vD = *(const float4*)&sV[bf][j + 3][d4 * 4];
            #pragma unroll
            for (int r = 0; r < 4; r++) {
                float4 a4 = *(const float4*)&sA[bf][4 * rg + r][j];
                acc[r].x = fmaf(a4.x, vA.x, acc[r].x);
                acc[r].y = fmaf(a4.x, vA.y, acc[r].y);
                acc[r].z = fmaf(a4.x, vA.z, acc[r].z);
                acc[r].w = fmaf(a4.x, vA.w, acc[r].w);
                acc[r].x = fmaf(a4.y, vB.x, acc[r].x);
                acc[r].y = fmaf(a4.y, vB.y, acc[r].y);
                acc[r].z = fmaf(a4.y, vB.z, acc[r].z);
                acc[r].w = fmaf(a4.y, vB.w, acc[r].w);
                acc[r].x = fmaf(a4.z, vC.x, acc[r].x);
                acc[r].y = fmaf(a4.z, vC.y, acc[r].y);
                acc[r].z = fmaf(a4.z, vC.z, acc[r].z);
                acc[r].w = fmaf(a4.z, vC.w, acc[r].w);
                acc[r].x = fmaf(a4.w, vD.x, acc[r].x);
                acc[r].y = fmaf(a4.w, vD.y, acc[r].y);
                acc[r].z = fmaf(a4.w, vD.z, acc[r].z);
                acc[r].w = fmaf(a4.w, vD.w, acc[r].w);
            }
        }
        __syncthreads();
    }

    // combine jg partials, one row of the 4-row group at a time
    #pragma unroll
    for (int r = 0; r < 4; r++) {
        *(float4*)sP[jg][s] = acc[r];
        __syncthreads();
        if (jg == 0) {
            float4 t0 = *(const float4*)sP[0][s];
            float4 t1 = *(const float4*)sP[1][s];
            float4 t2 = *(const float4*)sP[2][s];
            float4 t3 = *(const float4*)sP[3][s];
            float4 o = make_float4(t0.x + t1.x + t2.x + t3.x,
                                   t0.y + t1.y + t2.y + t3.y,
                                   t0.z + t1.z + t2.z + t3.z,
                                   t0.w + t1.w + t2.w + t3.w);
            *(float4*)&out_ctx[(size_t)(r0 + 4 * rg + r) * DD + d0 + d4 * 4] = o;
        }
        __syncthreads();
    }
}

extern "C" void kernel_launch(void* const* d_in, const int* in_sizes, int n_in,
                              void* d_out, int out_size) {
    (void)in_sizes; (void)n_in; (void)out_size;
    const float* Q  = (const float*)d_in[0];
    const float* V  = (const float*)d_in[2];
    const float* Wm = (const float*)d_in[3];
    const float* vm = (const float*)d_in[4];
    float* out      = (float*)d_out;
    float* out_ctx  = out;              // context [B,S,D]
    float* out_att  = out + BS * DD;    // atten   [B,S,S]

    k0_wt    <<<64, 256>>>(Wm);
    k1_proj  <<<BS / 4, 256>>>(Q);
    k2_scores<<<BB * NP, 256>>>(vm);
    k3_av    <<<(BS / 32) * 8, 256>>>(V, out_ctx, out_att);
}